// round 10
// baseline (speedup 1.0000x reference)
#include <cuda_runtime.h>
#include <cuda_fp16.h>
#include <math_constants.h>
#include <cstdint>

#define BATCH 2
#define SEQ   2048
#define DIM   1024
#define HEADS 16
#define HD    64
#define ROWS  (BATCH*SEQ)   // 4096
#define LOG2E 1.4426950408889634f
#define SCALE2 (0.125f * LOG2E)

// ---------------------------------------------------------------------------
// Scratch
// ---------------------------------------------------------------------------
__device__ __align__(16) __half a_kv[ROWS*DIM], a_q[ROWS*DIM];
__device__ __align__(16) __half w_f[4][DIM*DIM];           // [k][n] fp16
__device__ __align__(16) __half h_K[ROWS*DIM], h_Q[ROWS*DIM], h_V[ROWS*DIM];
__device__ __align__(16) __half h_Y[ROWS*DIM];

// ---------------------------------------------------------------------------
// PTX helpers
// ---------------------------------------------------------------------------
__device__ __forceinline__ uint32_t smem_addr(const void* p) {
    return (uint32_t)__cvta_generic_to_shared(p);
}
__device__ __forceinline__ uint32_t h2exp2(uint32_t x) {
    uint32_t d;
    asm volatile("ex2.approx.f16x2 %0, %1;" : "=r"(d) : "r"(x));
    return d;
}
__device__ __forceinline__ float2 h2_to_f2(uint32_t u) {
    __half2 h;
    memcpy(&h, &u, 4);
    return __half22float2(h);
}
#define CP16(dst, src) \
    asm volatile("cp.async.cg.shared.global [%0], [%1], 16;" \
                 :: "r"(smem_addr(dst)), "l"(src))
#define CP_COMMIT() asm volatile("cp.async.commit_group;" ::: "memory")
#define CP_WAIT(n)  asm volatile("cp.async.wait_group %0;" :: "n"(n) : "memory")

__device__ __forceinline__ void ldsm_x4(uint32_t& r0, uint32_t& r1,
                                        uint32_t& r2, uint32_t& r3, uint32_t a) {
    asm volatile("ldmatrix.sync.aligned.m8n8.x4.shared.b16 {%0,%1,%2,%3}, [%4];"
                 : "=r"(r0), "=r"(r1), "=r"(r2), "=r"(r3) : "r"(a));
}
__device__ __forceinline__ void ldsm_x4_t(uint32_t& r0, uint32_t& r1,
                                          uint32_t& r2, uint32_t& r3, uint32_t a) {
    asm volatile("ldmatrix.sync.aligned.m8n8.x4.trans.shared.b16 {%0,%1,%2,%3}, [%4];"
                 : "=r"(r0), "=r"(r1), "=r"(r2), "=r"(r3) : "r"(a));
}
__device__ __forceinline__ void ldsm_x2_t(uint32_t& r0, uint32_t& r1, uint32_t a) {
    asm volatile("ldmatrix.sync.aligned.m8n8.x2.trans.shared.b16 {%0,%1}, [%2];"
                 : "=r"(r0), "=r"(r1) : "r"(a));
}
// fp32-accumulate HMMA (GEMMs)
__device__ __forceinline__ void mma_fp16(float* d, const uint32_t* a, const uint32_t* b) {
    asm volatile("mma.sync.aligned.m16n8k16.row.col.f32.f16.f16.f32 "
                 "{%0,%1,%2,%3}, {%4,%5,%6,%7}, {%8,%9}, {%0,%1,%2,%3};"
                 : "+f"(d[0]), "+f"(d[1]), "+f"(d[2]), "+f"(d[3])
                 : "r"(a[0]), "r"(a[1]), "r"(a[2]), "r"(a[3]), "r"(b[0]), "r"(b[1]));
}
// fp16-accumulate HMMA (attention)
__device__ __forceinline__ void mma_h16(uint32_t* d, const uint32_t* a, const uint32_t* b) {
    asm volatile("mma.sync.aligned.m16n8k16.row.col.f16.f16.f16.f16 "
                 "{%0,%1}, {%2,%3,%4,%5}, {%6,%7}, {%0,%1};"
                 : "+r"(d[0]), "+r"(d[1])
                 : "r"(a[0]), "r"(a[1]), "r"(a[2]), "r"(a[3]), "r"(b[0]), "r"(b[1]));
}

// ---------------------------------------------------------------------------
// Pre-processing: fp32 -> fp16 converts
// ---------------------------------------------------------------------------
__global__ __launch_bounds__(256) void convert_acts(const float* __restrict__ kv,
                                                    const float* __restrict__ q)
{
    const int n4 = ROWS * DIM / 4;
    for (int i = blockIdx.x * blockDim.x + threadIdx.x; i < 2 * n4;
         i += gridDim.x * blockDim.x) {
        const float4* s4 = (i < n4) ? (const float4*)kv : (const float4*)q;
        __half2* d2 = (__half2*)((i < n4) ? a_kv : a_q);
        const int j = (i < n4) ? i : i - n4;
        float4 f = s4[j];
        d2[2*j]   = __floats2half2_rn(f.x, f.y);
        d2[2*j+1] = __floats2half2_rn(f.z, f.w);
    }
}

__global__ __launch_bounds__(256) void convert_w(const float* __restrict__ W0,
                                                 const float* __restrict__ W1,
                                                 const float* __restrict__ W2,
                                                 const float* __restrict__ W3)
{
    const int n4 = DIM * DIM / 4;
    const float* Ws[4] = { W0, W1, W2, W3 };
    for (int i = blockIdx.x * blockDim.x + threadIdx.x; i < 4 * n4;
         i += gridDim.x * blockDim.x) {
        const int wi = i / n4, j = i - wi * n4;
        float4 f = ((const float4*)Ws[wi])[j];
        __half2* d2 = (__half2*)w_f[wi];
        d2[2*j]   = __floats2half2_rn(f.x, f.y);
        d2[2*j+1] = __floats2half2_rn(f.z, f.w);
    }
}

// ---------------------------------------------------------------------------
// fp16 HMMA GEMM core: KC=64 chunks, 3-stage cp.async ring (unchanged R9).
// ---------------------------------------------------------------------------
#define AKS 72
#define BSTR 136
#define AT (128 * AKS)
#define BT (64 * BSTR)
#define STG (AT + BT)
#define NSTG_G 3
#define G16_DSMEM (NSTG_G * STG * 2)  // 107520 bytes
#define NCH (DIM / 64)

struct GemmCore {
    const __half* A;
    const __half* B;
    __half* smf;
    int row0, col0, tid, warp, lane, wy, wx;
    float acc[4][4][4];

    __device__ __forceinline__ void init() {
        #pragma unroll
        for (int i = 0; i < 4; i++)
            #pragma unroll
            for (int j = 0; j < 4; j++)
                #pragma unroll
                for (int k = 0; k < 4; k++) acc[i][j][k] = 0.f;
    }
    __device__ __forceinline__ void load_stage(int ch, int s) {
        __half* st = smf + s * STG;
        #pragma unroll
        for (int i = 0; i < 4; i++) {
            const int v = tid + i * 256;
            const int r = v >> 3, p = v & 7;
            CP16(st + r * AKS + p * 8,
                 A + (size_t)(row0 + r) * DIM + ch * 64 + p * 8);
        }
        #pragma unroll
        for (int i = 0; i < 4; i++) {
            const int v = tid + i * 256;
            const int r = v >> 4, p = v & 15;
            CP16(st + AT + r * BSTR + p * 8,
                 B + (size_t)(ch * 64 + r) * DIM + col0 + p * 8);
        }
        CP_COMMIT();
    }
    __device__ __forceinline__ void compute(int s) {
        const __half* sA = smf + s * STG;
        const __half* sB = sA + AT;
        #pragma unroll
        for (int ks = 0; ks < 4; ks++) {
            const int kcol = ks * 16 + (lane >> 4) * 8;
            uint32_t af[4][4];
            #pragma unroll
            for (int mi = 0; mi < 4; mi++) {
                const int ar = wy * 64 + mi * 16 + (lane & 15);
                ldsm_x4(af[mi][0], af[mi][1], af[mi][2], af[mi][3],
                        smem_addr(&sA[ar * AKS + kcol]));
            }
            uint32_t bf[4][2];
            #pragma unroll
            for (int nb = 0; nb < 2; nb++) {
                const int br = ks * 16 + (lane & 15);
                uint32_t r0, r1, r2, r3;
                ldsm_x4_t(r0, r1, r2, r3,
                          smem_addr(&sB[br * BSTR + wx * 32 + nb * 16 + (lane >> 4) * 8]));
                bf[2*nb][0] = r0; bf[2*nb][1] = r1;
                bf[2*nb+1][0] = r2; bf[2*nb+1][1] = r3;
            }
            #pragma unroll
            for (int mi = 0; mi < 4; mi++)
                #pragma unroll
                for (int nj = 0; nj < 4; nj++)
                    mma_fp16(acc[mi][nj], af[mi], bf[nj]);
        }
    }
    __device__ __forceinline__ void run() {
        init();
        load_stage(0, 0);
        load_stage(1, 1);
        for (int ch = 0; ch < NCH; ch++) {
            CP_WAIT(1);
            __syncthreads();
            if (ch + 2 < NCH) load_stage(ch + 2, (ch + 2) % 3);
            compute(ch % 3);
        }
    }
};

__global__ __launch_bounds__(256, 2) void gemm_qkv(const float* __restrict__ bk,
                                                   const float* __restrict__ bq,
                                                   const float* __restrict__ bv)
{
    extern __shared__ __half smf[];
    const int z = blockIdx.z;

    GemmCore gc;
    gc.A = (z == 1) ? a_q : a_kv;
    gc.B = w_f[z];
    gc.smf = smf;
    gc.tid = threadIdx.x;
    gc.warp = gc.tid >> 5; gc.lane = gc.tid & 31;
    gc.wy = gc.warp >> 2;  gc.wx = gc.warp & 3;
    gc.row0 = blockIdx.y * 128;
    gc.col0 = blockIdx.x * 128;
    gc.run();

    const float* bias = (z == 0) ? bk : (z == 1) ? bq : bv;
    __half* hOut = (z == 0) ? h_K : (z == 1) ? h_Q : h_V;
    const float scl = (z == 1) ? SCALE2 : 1.f;

    const int g = gc.lane >> 2, t = gc.lane & 3;
    #pragma unroll
    for (int mi = 0; mi < 4; mi++)
        #pragma unroll
        for (int nj = 0; nj < 4; nj++) {
            const int r   = gc.row0 + gc.wy * 64 + mi * 16 + g;
            const int col = gc.col0 + gc.wx * 32 + nj * 8 + 2 * t;
            const float b0 = __ldg(bias + col), b1 = __ldg(bias + col + 1);
            *(__half2*)&hOut[(size_t)r * DIM + col] =
                __floats2half2_rn((gc.acc[mi][nj][0] + b0) * scl,
                                  (gc.acc[mi][nj][1] + b1) * scl);
            *(__half2*)&hOut[(size_t)(r + 8) * DIM + col] =
                __floats2half2_rn((gc.acc[mi][nj][2] + b0) * scl,
                                  (gc.acc[mi][nj][3] + b1) * scl);
        }
}

__global__ __launch_bounds__(256, 2) void gemm_out(const float* __restrict__ bias,
                                                   float* __restrict__ Cext)
{
    extern __shared__ __half smf[];

    GemmCore gc;
    gc.A = h_Y;
    gc.B = w_f[3];
    gc.smf = smf;
    gc.tid = threadIdx.x;
    gc.warp = gc.tid >> 5; gc.lane = gc.tid & 31;
    gc.wy = gc.warp >> 2;  gc.wx = gc.warp & 3;
    gc.row0 = blockIdx.y * 128;
    gc.col0 = blockIdx.x * 128;
    gc.run();

    const int g = gc.lane >> 2, t = gc.lane & 3;
    #pragma unroll
    for (int mi = 0; mi < 4; mi++)
        #pragma unroll
        for (int nj = 0; nj < 4; nj++) {
            const int r   = gc.row0 + gc.wy * 64 + mi * 16 + g;
            const int col = gc.col0 + gc.wx * 32 + nj * 8 + 2 * t;
            const float b0 = __ldg(bias + col), b1 = __ldg(bias + col + 1);
            *(float2*)&Cext[(size_t)r * DIM + col] =
                make_float2(gc.acc[mi][nj][0] + b0, gc.acc[mi][nj][1] + b1);
            *(float2*)&Cext[(size_t)(r + 8) * DIM + col] =
                make_float2(gc.acc[mi][nj][2] + b0, gc.acc[mi][nj][3] + b1);
        }
}

// ---------------------------------------------------------------------------
// Flash attention: fp16-ACCUMULATE HMMA for S and per-tile PV/l (promoted to
// fp32 each 64-key tile). Static softmax, ex2.approx.f16x2 directly on the
// fp16 S fragments (no cvt). m32 warps, 3-stage cp.async ring. grid (16,16,2).
// ---------------------------------------------------------------------------
#define ASTR 72
#define KVT (64 * ASTR)
#define NSTG_A 3
#define ATT_DSMEM ((128 * ASTR + NSTG_A * 2 * KVT) * 2)   // 73728 bytes

__global__ __launch_bounds__(128) void attn_hmma()
{
    extern __shared__ __half smh[];
    __half* sQ = smh;
    __half* kvb = smh + 128 * ASTR;

    const int qb = blockIdx.x, h = blockIdx.y, b = blockIdx.z;
    const int tid = threadIdx.x;
    const int warp = tid >> 5, lane = tid & 31;
    const int g = lane >> 2, t = lane & 3;

    auto load_kv = [&](int kb, int s) {
        __half* st = kvb + s * 2 * KVT;
        #pragma unroll
        for (int i = 0; i < 4; i++) {
            const int v = tid + i * 128;
            const int r = v >> 3, p = v & 7;
            CP16(&st[r * ASTR + p * 8],
                 &h_K[(size_t)(b * SEQ + kb * 64 + r) * DIM + h * HD + p * 8]);
        }
        #pragma unroll
        for (int i = 0; i < 4; i++) {
            const int v = tid + i * 128;
            const int r = v >> 3, p = v & 7;
            CP16(&st[KVT + r * ASTR + p * 8],
                 &h_V[(size_t)(b * SEQ + kb * 64 + r) * DIM + h * HD + p * 8]);
        }
        CP_COMMIT();
    };

    #pragma unroll
    for (int i = 0; i < 8; i++) {
        const int v = tid + i * 128;
        const int r = v >> 3, p = v & 7;
        CP16(&sQ[r * ASTR + p * 8],
             &h_Q[(size_t)(b * SEQ + qb * 128 + r) * DIM + h * HD + p * 8]);
    }
    load_kv(0, 0);
    load_kv(1, 1);

    // ones-column init (V padding col 64 = 1.0h, cols 65-71 = 0), all stages
    for (int i = tid; i < NSTG_A * 64; i += 128) {
        const int s = i / 64, r = i % 64;
        uint4 ones = make_uint4(0x00003C00u, 0u, 0u, 0u);
        *(uint4*)&kvb[s * 2 * KVT + KVT + r * ASTR + 64] = ones;
    }

    CP_WAIT(1);
    __syncthreads();

    uint32_t qf[2][4][4];
    #pragma unroll
    for (int mi = 0; mi < 2; mi++)
        #pragma unroll
        for (int ks = 0; ks < 4; ks++) {
            const int qr = warp * 32 + mi * 16 + (lane & 15);
            ldsm_x4(qf[mi][ks][0], qf[mi][ks][1], qf[mi][ks][2], qf[mi][ks][3],
                    smem_addr(&sQ[qr * ASTR + ks * 16 + (lane >> 4) * 8]));
        }

    float oacc[2][8][4];
    float laccf[2][2];
    #pragma unroll
    for (int mi = 0; mi < 2; mi++) {
        #pragma unroll
        for (int j = 0; j < 8; j++)
            #pragma unroll
            for (int k = 0; k < 4; k++) oacc[mi][j][k] = 0.f;
        laccf[mi][0] = 0.f; laccf[mi][1] = 0.f;
    }

    for (int kb = 0; kb < SEQ / 64; kb++) {
        if (kb > 0) { CP_WAIT(1); __syncthreads(); }
        if (kb + 2 < SEQ / 64) load_kv(kb + 2, (kb + 2) % NSTG_A);

        const __half* sK = kvb + (kb % NSTG_A) * 2 * KVT;
        const __half* sV = sK + KVT;

        // S = Q K^T in fp16 accumulators
        uint32_t s16[2][8][2];
        #pragma unroll
        for (int mi = 0; mi < 2; mi++)
            #pragma unroll
            for (int j = 0; j < 8; j++) { s16[mi][j][0] = 0u; s16[mi][j][1] = 0u; }

        #pragma unroll
        for (int ks = 0; ks < 4; ks++) {
            const int kcol = ks * 16 + (lane >> 4) * 8;
            uint32_t bk[8][2];
            #pragma unroll
            for (int nb = 0; nb < 4; nb++) {
                const int kr = nb * 16 + (lane & 7) + ((lane >> 3) & 1) * 8;
                uint32_t r0, r1, r2, r3;
                ldsm_x4(r0, r1, r2, r3, smem_addr(&sK[kr * ASTR + kcol]));
                bk[2*nb][0] = r0; bk[2*nb][1] = r2;
                bk[2*nb+1][0] = r1; bk[2*nb+1][1] = r3;
            }
            #pragma unroll
            for (int mi = 0; mi < 2; mi++)
                #pragma unroll
                for (int j = 0; j < 8; j++)
                    mma_h16(s16[mi][j], qf[mi][ks], bk[j]);
        }

        // P = 2^S in place: fp16 D fragments ARE fp16x2 A fragments
        #pragma unroll
        for (int mi = 0; mi < 2; mi++)
            #pragma unroll
            for (int j = 0; j < 8; j++) {
                s16[mi][j][0] = h2exp2(s16[mi][j][0]);   // rows g
                s16[mi][j][1] = h2exp2(s16[mi][j][1]);   // rows g+8
            }

        // O_tile = P V ; l_tile = P @ ones — fp16 accumulators within the tile
        uint32_t pv16[2][8][2];
        uint32_t l16[2][2];
        #pragma unroll
        for (int mi = 0; mi < 2; mi++) {
            #pragma unroll
            for (int j = 0; j < 8; j++) { pv16[mi][j][0] = 0u; pv16[mi][j][1] = 0u; }
            l16[mi][0] = 0u; l16[mi][1] = 0u;
        }

        #pragma unroll
        for (int ks = 0; ks < 4; ks++) {
            uint32_t bv[8][2];
            #pragma unroll
            for (int hb = 0; hb < 4; hb++) {
                const int vr = ks * 16 + (lane & 15);
                uint32_t r0, r1, r2, r3;
                ldsm_x4_t(r0, r1, r2, r3,
                          smem_addr(&sV[vr * ASTR + hb * 16 + (lane >> 4) * 8]));
                bv[2*hb][0] = r0; bv[2*hb][1] = r1;
                bv[2*hb+1][0] = r2; bv[2*hb+1][1] = r3;
            }
            uint32_t bo[2];
            ldsm_x2_t(bo[0], bo[1],
                      smem_addr(&sV[(ks * 16 + (lane & 15)) * ASTR + 64]));

            #pragma unroll
            for (int mi = 0; mi < 2; mi++) {
                uint32_t a[4] = { s16[mi][2*ks][0], s16[mi][2*ks][1],
                                  s16[mi][2*ks+1][0], s16[mi][2*ks+1][1] };
                #pragma unroll
                for (int j = 0; j < 8; j++) mma_h16(pv16[mi][j], a, bv[j]);
                mma_h16(l16[mi], a, bo);
            }
        }

        // Promote tile partials to fp32
        #pragma unroll
        for (int mi = 0; mi < 2; mi++) {
            #pragma unroll
            for (int j = 0; j < 8; j++) {
                float2 u0 = h2_to_f2(pv16[mi][j][0]);
                float2 u1 = h2_to_f2(pv16[mi][j][1]);
                oacc[mi][j][0] += u0.x; oacc[mi][j][1] += u0.y;
                oacc[mi][j][2] += u1.x; oacc[mi][j][3] += u1.y;
            }
            laccf[mi][0] += h2_to_f2(l16[mi][0]).x;   // c0 (row g,   col 64)
            laccf[mi][1] += h2_to_f2(l16[mi][1]).x;   // c2 (row g+8, col 64)
        }
    }

    // Epilogue per m16 half
    #pragma unroll
    for (int mi = 0; mi < 2; mi++) {
        const float lv0 = __shfl_sync(0xffffffffu, laccf[mi][0], lane & 28);
        const float lv1 = __shfl_sync(0xffffffffu, laccf[mi][1], lane & 28);
        const float inv0 = 1.f / lv0, inv1 = 1.f / lv1;
        const size_t r0 = (size_t)(b * SEQ + qb * 128 + warp * 32 + mi * 16 + g);
        #pragma unroll
        for (int j = 0; j < 8; j++) {
            const int col = h * HD + j * 8 + 2 * t;
            *(__half2*)&h_Y[r0 * DIM + col] =
                __floats2half2_rn(oacc[mi][j][0] * inv0, oacc[mi][j][1] * inv0);
            *(__half2*)&h_Y[(r0 + 8) * DIM + col] =
                __floats2half2_rn(oacc[mi][j][2] * inv1, oacc[mi][j][3] * inv1);
        }
    }
}

// ---------------------------------------------------------------------------
// Launch
// ---------------------------------------------------------------------------
extern "C" void kernel_launch(void* const* d_in, const int* in_sizes, int n_in,
                              void* d_out, int out_size)
{
    const float* kv = (const float*)d_in[0];
    const float* q  = (const float*)d_in[1];
    const float* Wk = (const float*)d_in[2];
    const float* bk = (const float*)d_in[3];
    const float* Wq = (const float*)d_in[4];
    const float* bq = (const float*)d_in[5];
    const float* Wv = (const float*)d_in[6];
    const float* bv = (const float*)d_in[7];
    const float* Wp = (const float*)d_in[8];
    const float* bp = (const float*)d_in[9];
    float* out = (float*)d_out;

    cudaFuncSetAttribute(gemm_qkv, cudaFuncAttributeMaxDynamicSharedMemorySize, G16_DSMEM);
    cudaFuncSetAttribute(gemm_out, cudaFuncAttributeMaxDynamicSharedMemorySize, G16_DSMEM);
    cudaFuncSetAttribute(attn_hmma, cudaFuncAttributeMaxDynamicSharedMemorySize, ATT_DSMEM);

    convert_acts<<<1024, 256>>>(kv, q);
    convert_w<<<1024, 256>>>(Wk, Wq, Wv, Wp);

    dim3 qkv_grid(DIM / 128, ROWS / 128, 3);   // (8, 32, 3)
    gemm_qkv<<<qkv_grid, 256, G16_DSMEM>>>(bk, bq, bv);

    dim3 agrid(SEQ / 128, HEADS, BATCH);       // (16, 16, 2)
    attn_hmma<<<agrid, 128, ATT_DSMEM>>>();

    dim3 ogrid(DIM / 128, ROWS / 128);         // (8, 32)
    gemm_out<<<ogrid, 256, G16_DSMEM>>>(bp, out);
}